// round 11
// baseline (speedup 1.0000x reference)
#include <cuda_runtime.h>
#include <cstdint>

#define BB 16
#define NN 25200
#define NCC 80
#define ROWW 85
#define MAXDET 300
#define NPRE 1024
#define GCAP 8192
#define NBINS 1536
#define BASE_BITS 0x3EC00000u
#define HSHIFT 13
#define RPB 256
#define GRID_X ((NN + RPB - 1) / RPB)
#define CAPC 192

typedef unsigned long long u64;
typedef unsigned int u32;
typedef unsigned short u16;

// ---------------- scratch (zero-init at load; each kernel re-zeroes what it consumed) ----------------
static __device__ u32 g_hist[BB * NBINS];
static __device__ u32 g_preCnt[BB];
static __device__ u64 g_preRaw[BB * GCAP];
static __device__ u64 g_preSorted[BB * NPRE];
static __device__ u32 g_preN[BB];

__device__ __forceinline__ int score_bin(u32 bits) {
    int bin = (int)((bits - BASE_BITS) >> HSHIFT);
    return bin > (NBINS - 1) ? (NBINS - 1) : bin;
}
#define PB90 (score_bin(0x3F666666u))   /* bin of 0.90f */
#define PB96 (score_bin(0x3F75C28Fu))   /* bin of 0.96f */

__device__ __forceinline__ void warp_store(int b, bool pass, u64 key) {
    u32 m = __ballot_sync(0xffffffffu, pass);
    if (!m) return;
    int lane = threadIdx.x & 31;
    int leader = __ffs(m) - 1;
    u32 base = 0;
    if (lane == leader) base = atomicAdd(&g_preCnt[b], (u32)__popc(m));
    base = __shfl_sync(0xffffffffu, base, leader);
    if (pass) {
        u32 slot = base + __popc(m & ((1u << lane) - 1u));
        if (slot < GCAP) g_preRaw[(size_t)b * GCAP + slot] = key;
    }
}

// ---------------- kernel 1: streaming pass ----------------
// obj prefilter (1 sector/row), compact passing rows to shared, then warps
// read cls scores only for passing rows. histogram scores > 0.9; store
// candidates with bin > PB96 into g_preRaw.
__global__ void __launch_bounds__(256) k_pass1(const float* __restrict__ pred) {
    __shared__ u32 sh[NBINS];
    __shared__ float sobj[RPB];
    __shared__ u16 srow[RPB];
    __shared__ u32 srn;
    int b = blockIdx.y, tid = threadIdx.x;
    int row0 = blockIdx.x * RPB;
    for (int i = tid; i < NBINS; i += 256) sh[i] = 0;
    if (tid == 0) srn = 0;
    __syncthreads();
    int row = row0 + tid;
    if (row < NN) {
        float obj = pred[((size_t)b * NN + row) * ROWW + 4];
        if (obj > 0.4f) {
            u32 p = atomicAdd(&srn, 1u);
            srow[p] = (u16)tid;
            sobj[p] = obj;
        }
    }
    __syncthreads();
    int nr = (int)srn;
    int warp = tid >> 5, lane = tid & 31;
    for (int i = warp; i < nr; i += 8) {
        int rowg = row0 + srow[i];
        const float* q = pred + ((size_t)b * NN + rowg) * ROWW;
        float obj = sobj[i];
#pragma unroll
        for (int k = 0; k < 3; k++) {
            int c = k * 32 + lane;
            bool pass = false;
            u64 key = 0;
            if (c < NCC) {
                float s = __fmul_rn(q[5 + c], obj);
                if (s > 0.9f) {
                    u32 bits = __float_as_uint(s);
                    int bin = score_bin(bits);
                    atomicAdd(&sh[bin], 1u);
                    if (bin > PB96) {
                        pass = true;
                        u32 flat = (u32)rowg * NCC + (u32)c;
                        key = ((u64)bits << 21) | (u64)(0x1FFFFFu - flat);
                    }
                }
            }
            warp_store(b, pass, key);
        }
    }
    __syncthreads();
    for (int i = tid; i < NBINS; i += 256)
        if (sh[i]) atomicAdd(&g_hist[b * NBINS + i], sh[i]);
}

// ---------------- kernel 2: select + (rescue) + sort, one block/batch ----------------
__global__ void __launch_bounds__(1024) k_main(const float* __restrict__ pred) {
    extern __shared__ u64 sk[];          // GCAP keys (64 KB dynamic)
    __shared__ u32 h[NBINS];
    __shared__ u32 part[256];
    __shared__ int sbeta;
    __shared__ u32 scount;
    int b = blockIdx.x, tid = threadIdx.x;
    int warp = tid >> 5, lane = tid & 31;

    // load histogram; zero the global copy (cleanup for next replay)
    for (int i = tid; i < NBINS; i += 1024) {
        h[i] = g_hist[b * NBINS + i];
        g_hist[b * NBINS + i] = 0;
    }
    if (tid == 0) scount = 0;
    __syncthreads();

    // beta over complete bins (> PB90 only)
    if (tid < 256) {
        u32 ps = 0;
        for (int k = 0; k < 6; k++) {
            int bin = tid * 6 + k;
            ps += (bin > PB90) ? h[bin] : 0u;
        }
        part[tid] = ps;
    }
    __syncthreads();
    if (tid == 0) {
        u32 cum = 0; int beta = -1;
        for (int t = 255; t >= 0; --t) {
            if (cum + part[t] >= (u32)NPRE) {
                for (int bin = t * 6 + 5; bin >= t * 6; --bin) {
                    u32 c = (bin > PB90) ? h[bin] : 0u;
                    if (cum + c >= (u32)NPRE) { beta = bin; break; }
                    cum += c;
                }
                break;
            }
            cum += part[t];
        }
        if (beta <= PB96) beta = -1;      // need rescue
        sbeta = beta;
    }
    __syncthreads();

    if (sbeta < 0) {
        // ---- rescue path (exact; block-uniform branch) ----
        // complete histogram for scores in (0.4, 0.9]
        for (int row = warp; row < NN; row += 32) {
            const float* q = pred + ((size_t)b * NN + row) * ROWW;
            float obj = q[4];
            if (obj > 0.4f) {
#pragma unroll
                for (int k = 0; k < 3; k++) {
                    int c = k * 32 + lane;
                    if (c < NCC) {
                        float s = __fmul_rn(q[5 + c], obj);
                        if (s > 0.4f && !(s > 0.9f))
                            atomicAdd(&h[score_bin(__float_as_uint(s))], 1u);
                    }
                }
            }
        }
        __syncthreads();
        if (tid == 0) {
            u32 cum = 0; int beta = 0;
            for (int bin = NBINS - 1; bin >= 0; --bin) {
                u32 c = h[bin];
                if (cum + c >= (u32)NPRE) { beta = bin; break; }
                cum += c;
            }
            sbeta = beta;
            g_preCnt[b] = 0;             // regather replaces raw buffer
        }
        __syncthreads();
        int beta = sbeta;
        for (int row = warp; row < NN; row += 32) {
            const float* q = pred + ((size_t)b * NN + row) * ROWW;
            float obj = q[4];
            bool rowok = (obj > 0.4f);
#pragma unroll
            for (int k = 0; k < 3; k++) {
                int c = k * 32 + lane;
                bool pass = false;
                u64 key = 0;
                if (rowok && c < NCC) {
                    float s = __fmul_rn(q[5 + c], obj);
                    if (s > 0.4f) {
                        u32 bits = __float_as_uint(s);
                        if (score_bin(bits) >= beta) {
                            pass = true;
                            u32 flat = (u32)row * NCC + (u32)c;
                            key = ((u64)bits << 21) | (u64)(0x1FFFFFu - flat);
                        }
                    }
                }
                warp_store(b, pass, key);
            }
        }
        __syncthreads();
    }

    // ---- filter raw by bin >= beta, bitonic sort desc, keep NPRE ----
    int beta = sbeta;
    u32 cnt = min(g_preCnt[b], (u32)GCAP);
    for (u32 i = tid; i < cnt; i += 1024) {
        u64 key = g_preRaw[(size_t)b * GCAP + i];
        if (score_bin((u32)(key >> 21)) >= beta) {
            u32 p = atomicAdd(&scount, 1u);
            sk[p] = key;
        }
    }
    __syncthreads();
    u32 fc = min(scount, (u32)GCAP);
    u32 P = 2;
    while (P < fc) P <<= 1;
    for (u32 i = fc + tid; i < P; i += 1024) sk[i] = 0ull;
    __syncthreads();
    for (u32 k = 2; k <= P; k <<= 1) {
        for (u32 j = k >> 1; j; j >>= 1) {
            for (u32 i = tid; i < P; i += 1024) {
                u32 l = i ^ j;
                if (l > i) {
                    u64 a = sk[i], c = sk[l];
                    bool desc = ((i & k) == 0);
                    if ((a < c) == desc) { sk[i] = c; sk[l] = a; }
                }
            }
            __syncthreads();
        }
    }
    if (tid == 0) {
        g_preN[b] = min(fc, (u32)NPRE);
        g_preCnt[b] = 0;                 // cleanup for next replay
    }
    for (int i = tid; i < NPRE; i += 1024)
        g_preSorted[(size_t)b * NPRE + i] = (i < (int)P) ? sk[i] : 0ull;
}

// ---------------- kernel 3: NMS + final emit, one block/batch ----------------
__global__ void __launch_bounds__(256) k_nmsfinal(const float* __restrict__ pred,
                                                  float* __restrict__ out) {
    __shared__ u64 skeys[NPRE];               // 8 KB
    __shared__ unsigned char scls[NPRE];      // 1 KB
    __shared__ unsigned char skeep[NPRE];     // 1 KB
    __shared__ u16 spos[8][CAPC];             // 3 KB
    __shared__ float4 sbox[8][CAPC];          // 24 KB
    __shared__ float sarea[8][CAPC];          // 6 KB
    __shared__ unsigned char ssup[8][CAPC];   // 1.5 KB
    __shared__ u32 spart[256];                // 1 KB
    int b = blockIdx.x, tid = threadIdx.x;
    int w = tid >> 5, lane = tid & 31;
    u32 N = g_preN[b];

    for (int i = tid; i < NPRE; i += 256) {
        u64 key = g_preSorted[(size_t)b * NPRE + i];
        skeys[i] = key;
        u32 flat = 0x1FFFFFu - (u32)(key & 0x1FFFFFu);
        scls[i] = (i < (int)N) ? (unsigned char)(flat % NCC) : (unsigned char)0xFF;
        skeep[i] = 0;
    }
    __syncthreads();

    // each warp handles 10 classes sequentially
    for (int t = 0; t < 10; t++) {
        int myc = w * 10 + t;
        // collect members of class myc (in sorted order)
        u32 base = 0;
        for (u32 i = lane; i < ((N + 31) & ~31u); i += 32) {
            bool match = (i < N) && (scls[i] == (unsigned char)myc);
            u32 m = __ballot_sync(0xffffffffu, match);
            if (match) {
                u32 idx = base + __popc(m & ((1u << lane) - 1u));
                if (idx < CAPC) spos[w][idx] = (u16)i;
            }
            base += __popc(m);
        }
        u32 cnt = min(base, (u32)CAPC);
        float coff = (float)myc * 4096.0f;
        for (u32 j = lane; j < cnt; j += 32) {
            u32 i = spos[w][j];
            u32 flat = 0x1FFFFFu - (u32)(skeys[i] & 0x1FFFFFu);
            u32 n = flat / NCC;
            const float* q = pred + ((size_t)b * NN + n) * ROWW;
            float cx = q[0], cy = q[1], ww = q[2], hh = q[3];
            float x1 = __fsub_rn(cx, __fmul_rn(0.5f, ww));
            float y1 = __fsub_rn(cy, __fmul_rn(0.5f, hh));
            float x2 = __fadd_rn(cx, __fmul_rn(0.5f, ww));
            float y2 = __fadd_rn(cy, __fmul_rn(0.5f, hh));
            float ox1 = __fadd_rn(x1, coff), oy1 = __fadd_rn(y1, coff);
            float ox2 = __fadd_rn(x2, coff), oy2 = __fadd_rn(y2, coff);
            sbox[w][j] = make_float4(ox1, oy1, ox2, oy2);
            sarea[w][j] = __fmul_rn(__fsub_rn(ox2, ox1), __fsub_rn(oy2, oy1));
            ssup[w][j] = 0;
        }
        __syncwarp();
        for (u32 m = 0; m < cnt; m++) {
            if (ssup[w][m]) continue;
            if (lane == 0) skeep[spos[w][m]] = 1;
            float4 bm = sbox[w][m];
            float am = sarea[w][m];
            for (u32 j = m + 1 + lane; j < cnt; j += 32) {
                if (ssup[w][j]) continue;
                float4 bj = sbox[w][j];
                float ltx = fmaxf(bm.x, bj.x), lty = fmaxf(bm.y, bj.y);
                float rbx = fminf(bm.z, bj.z), rby = fminf(bm.w, bj.w);
                float wx = fmaxf(__fsub_rn(rbx, ltx), 0.0f);
                float wy = fmaxf(__fsub_rn(rby, lty), 0.0f);
                float inter = __fmul_rn(wx, wy);
                if (inter > 0.0f) {
                    float den = __fadd_rn(__fsub_rn(__fadd_rn(am, sarea[w][j]), inter), 1e-9f);
                    if (__fdiv_rn(inter, den) > 0.5f) ssup[w][j] = 1;
                }
            }
            __syncwarp();
        }
    }
    __syncthreads();

    // prefix scan over keep flags; emit first 300 in prefix (score) order
    float* ob = out + (size_t)b * MAXDET * 6;
    for (int k = tid; k < MAXDET * 6; k += 256) ob[k] = 0.0f;
    u32 s = 0;
    unsigned char f[4];
#pragma unroll
    for (int t = 0; t < 4; t++) {
        u32 i = tid * 4 + t;
        f[t] = skeep[i];
        s += f[t];
    }
    spart[tid] = s;
    __syncthreads();
    for (int off = 1; off < 256; off <<= 1) {
        u32 v = (tid >= off) ? spart[tid - off] : 0;
        __syncthreads();
        spart[tid] += v;
        __syncthreads();
    }
    u32 r = spart[tid] - s;
#pragma unroll
    for (int t = 0; t < 4; t++) {
        u32 i = tid * 4 + t;
        if (f[t]) {
            if (r < (u32)MAXDET) {
                u64 key = skeys[i];
                u32 flat = 0x1FFFFFu - (u32)(key & 0x1FFFFFu);
                u32 n = flat / NCC, c = flat - n * NCC;
                const float* q = pred + ((size_t)b * NN + n) * ROWW;
                float cx = q[0], cy = q[1], ww = q[2], hh = q[3];
                float* o = ob + r * 6;
                o[0] = __fsub_rn(cx, __fmul_rn(0.5f, ww));
                o[1] = __fsub_rn(cy, __fmul_rn(0.5f, hh));
                o[2] = __fadd_rn(cx, __fmul_rn(0.5f, ww));
                o[3] = __fadd_rn(cy, __fmul_rn(0.5f, hh));
                o[4] = __uint_as_float((u32)(key >> 21));
                o[5] = (float)c;
            }
            r++;
        }
    }
}

extern "C" void kernel_launch(void* const* d_in, const int* in_sizes, int n_in,
                              void* d_out, int out_size) {
    const float* pred = (const float*)d_in[0];
    float* out = (float*)d_out;
    (void)in_sizes; (void)n_in; (void)out_size;

    cudaFuncSetAttribute(k_main, cudaFuncAttributeMaxDynamicSharedMemorySize, GCAP * 8);

    k_pass1<<<dim3(GRID_X, BB), 256>>>(pred);
    k_main<<<BB, 1024, GCAP * 8>>>(pred);
    k_nmsfinal<<<BB, 256>>>(pred, out);
}

// round 13
// speedup vs baseline: 1.3262x; 1.3262x over previous
#include <cuda_runtime.h>
#include <cstdint>

#define BB 16
#define NN 25200
#define NCC 80
#define ROWW 85
#define MAXDET 300
#define NPRE 1024
#define GCAP 8192
#define NBINS 1536
#define BASE_BITS 0x3EC00000u
#define HSHIFT 13
#define RPB 256
#define GRID_X ((NN + RPB - 1) / RPB)
#define CAPC 128

typedef unsigned long long u64;
typedef unsigned int u32;
typedef unsigned short u16;

// ---------------- scratch (zero-init at load; kernels re-zero what they consume) ----------------
static __device__ u32 g_hist[BB * NBINS];
static __device__ u32 g_preCnt[BB];
static __device__ u64 g_preRaw[BB * GCAP];
static __device__ u64 g_preSorted[BB * NPRE];
static __device__ u32 g_preN[BB];
static __device__ unsigned char g_keep[BB * NPRE];

__device__ __forceinline__ int score_bin(u32 bits) {
    int bin = (int)((bits - BASE_BITS) >> HSHIFT);
    return bin > (NBINS - 1) ? (NBINS - 1) : bin;
}
#define PB90 (score_bin(0x3F666666u))   /* bin of 0.90f */
#define PB96 (score_bin(0x3F75C28Fu))   /* bin of 0.96f */

__device__ __forceinline__ void warp_store(int b, bool pass, u64 key) {
    u32 m = __ballot_sync(0xffffffffu, pass);
    if (!m) return;
    int lane = threadIdx.x & 31;
    int leader = __ffs(m) - 1;
    u32 base = 0;
    if (lane == leader) base = atomicAdd(&g_preCnt[b], (u32)__popc(m));
    base = __shfl_sync(0xffffffffu, base, leader);
    if (pass) {
        u32 slot = base + __popc(m & ((1u << lane) - 1u));
        if (slot < GCAP) g_preRaw[(size_t)b * GCAP + slot] = key;
    }
}

// ---------------- kernel 1: streaming pass (flat work queue) ----------------
// Phase A: 256 threads load obj for 256 rows (full MLP), compact passing rows.
// Phase B: all threads stride a flat nr*80 (row,class) queue — one independent
// coalesced load per element per iteration. Histogram s>0.9; store bin>PB96.
__global__ void __launch_bounds__(256) k_pass1(const float* __restrict__ pred) {
    __shared__ u32 sh[NBINS];
    __shared__ float sobj[RPB];
    __shared__ u16 srow[RPB];
    __shared__ u32 srn;
    int b = blockIdx.y, tid = threadIdx.x;
    int row0 = blockIdx.x * RPB;
    for (int i = tid; i < NBINS; i += 256) sh[i] = 0;
    if (tid == 0) srn = 0;
    __syncthreads();
    int row = row0 + tid;
    if (row < NN) {
        float obj = pred[((size_t)b * NN + row) * ROWW + 4];
        if (obj > 0.4f) {
            u32 p = atomicAdd(&srn, 1u);
            srow[p] = (u16)tid;
            sobj[p] = obj;
        }
    }
    __syncthreads();
    int nr = (int)srn;
    int total = nr * NCC;
    int totalR = (total + 255) & ~255;   // keep full warps converged for warp_store
    const float* pb = pred + (size_t)b * NN * ROWW;
#pragma unroll 2
    for (int e = tid; e < totalR; e += 256) {
        bool pass = false;
        u64 key = 0;
        if (e < total) {
            int i = e / NCC;
            int c = e - i * NCC;
            int rowg = row0 + srow[i];
            float s = __fmul_rn(pb[(size_t)rowg * ROWW + 5 + c], sobj[i]);
            if (s > 0.9f) {
                u32 bits = __float_as_uint(s);
                int bin = score_bin(bits);
                atomicAdd(&sh[bin], 1u);
                if (bin > PB96) {
                    pass = true;
                    u32 flat = (u32)rowg * NCC + (u32)c;
                    key = ((u64)bits << 21) | (u64)(0x1FFFFFu - flat);
                }
            }
        }
        warp_store(b, pass, key);
    }
    __syncthreads();
    for (int i = tid; i < NBINS; i += 256)
        if (sh[i]) atomicAdd(&g_hist[b * NBINS + i], sh[i]);
}

// ---------------- kernel 2: select + (rescue) + sort, one block/batch ----------------
__global__ void __launch_bounds__(1024) k_main(const float* __restrict__ pred) {
    extern __shared__ u64 sk[];          // GCAP keys (64 KB dynamic)
    __shared__ u32 h[NBINS];
    __shared__ u32 part[256];
    __shared__ int sbeta;
    __shared__ u32 scount;
    int b = blockIdx.x, tid = threadIdx.x;
    int warp = tid >> 5, lane = tid & 31;

    // load histogram; zero global copy + keep flags (replay cleanliness)
    for (int i = tid; i < NBINS; i += 1024) {
        h[i] = g_hist[b * NBINS + i];
        g_hist[b * NBINS + i] = 0;
    }
    for (int i = tid; i < NPRE / 4; i += 1024)
        ((u32*)g_keep)[b * (NPRE / 4) + i] = 0;
    if (tid == 0) scount = 0;
    __syncthreads();

    // beta over complete bins (> PB90 only)
    if (tid < 256) {
        u32 ps = 0;
        for (int k = 0; k < 6; k++) {
            int bin = tid * 6 + k;
            ps += (bin > PB90) ? h[bin] : 0u;
        }
        part[tid] = ps;
    }
    __syncthreads();
    if (tid == 0) {
        u32 cum = 0; int beta = -1;
        for (int t = 255; t >= 0; --t) {
            if (cum + part[t] >= (u32)NPRE) {
                for (int bin = t * 6 + 5; bin >= t * 6; --bin) {
                    u32 c = (bin > PB90) ? h[bin] : 0u;
                    if (cum + c >= (u32)NPRE) { beta = bin; break; }
                    cum += c;
                }
                break;
            }
            cum += part[t];
        }
        if (beta <= PB96) beta = -1;      // need rescue
        sbeta = beta;
    }
    __syncthreads();

    if (sbeta < 0) {
        // ---- exact rescue (block-uniform; effectively never taken) ----
        for (int row = warp; row < NN; row += 32) {
            const float* q = pred + ((size_t)b * NN + row) * ROWW;
            float obj = q[4];
            if (obj > 0.4f) {
#pragma unroll
                for (int k = 0; k < 3; k++) {
                    int c = k * 32 + lane;
                    if (c < NCC) {
                        float s = __fmul_rn(q[5 + c], obj);
                        if (s > 0.4f && !(s > 0.9f))
                            atomicAdd(&h[score_bin(__float_as_uint(s))], 1u);
                    }
                }
            }
        }
        __syncthreads();
        if (tid == 0) {
            u32 cum = 0; int beta = 0;
            for (int bin = NBINS - 1; bin >= 0; --bin) {
                u32 c = h[bin];
                if (cum + c >= (u32)NPRE) { beta = bin; break; }
                cum += c;
            }
            sbeta = beta;
            g_preCnt[b] = 0;
        }
        __syncthreads();
        int beta = sbeta;
        for (int row = warp; row < NN; row += 32) {
            const float* q = pred + ((size_t)b * NN + row) * ROWW;
            float obj = q[4];
            bool rowok = (obj > 0.4f);
#pragma unroll
            for (int k = 0; k < 3; k++) {
                int c = k * 32 + lane;
                bool pass = false;
                u64 key = 0;
                if (rowok && c < NCC) {
                    float s = __fmul_rn(q[5 + c], obj);
                    if (s > 0.4f) {
                        u32 bits = __float_as_uint(s);
                        if (score_bin(bits) >= beta) {
                            pass = true;
                            u32 flat = (u32)row * NCC + (u32)c;
                            key = ((u64)bits << 21) | (u64)(0x1FFFFFu - flat);
                        }
                    }
                }
                warp_store(b, pass, key);
            }
        }
        __syncthreads();
    }

    // ---- filter raw by bin >= beta, bitonic sort desc, keep NPRE ----
    int beta = sbeta;
    u32 cnt = min(g_preCnt[b], (u32)GCAP);
    for (u32 i = tid; i < cnt; i += 1024) {
        u64 key = g_preRaw[(size_t)b * GCAP + i];
        if (score_bin((u32)(key >> 21)) >= beta) {
            u32 p = atomicAdd(&scount, 1u);
            sk[p] = key;
        }
    }
    __syncthreads();
    u32 fc = min(scount, (u32)GCAP);
    u32 P = 2;
    while (P < fc) P <<= 1;
    for (u32 i = fc + tid; i < P; i += 1024) sk[i] = 0ull;
    __syncthreads();
    for (u32 k = 2; k <= P; k <<= 1) {
        for (u32 j = k >> 1; j; j >>= 1) {
            for (u32 i = tid; i < P; i += 1024) {
                u32 l = i ^ j;
                if (l > i) {
                    u64 a = sk[i], c = sk[l];
                    bool desc = ((i & k) == 0);
                    if ((a < c) == desc) { sk[i] = c; sk[l] = a; }
                }
            }
            __syncthreads();
        }
    }
    if (tid == 0) {
        g_preN[b] = min(fc, (u32)NPRE);
        g_preCnt[b] = 0;                 // replay cleanliness
    }
    for (int i = tid; i < NPRE; i += 1024)
        g_preSorted[(size_t)b * NPRE + i] = (i < (int)P) ? sk[i] : 0ull;
}

// ---------------- kernel 3: parallel NMS, warp per (class,batch) ----------------
__global__ void __launch_bounds__(256) k_nms(const float* __restrict__ pred) {
    __shared__ u16 spos[8][CAPC];
    __shared__ float4 sbox[8][CAPC];
    __shared__ float sarea[8][CAPC];
    __shared__ unsigned char ssup[8][CAPC];
    int b = blockIdx.y, tid = threadIdx.x;
    int w = tid >> 5, lane = tid & 31;
    int myc = blockIdx.x * 8 + w;
    u32 N = g_preN[b];
    const u64* ps = &g_preSorted[(size_t)b * NPRE];
    u32 base = 0;
    for (u32 i = lane; i < ((N + 31) & ~31u); i += 32) {
        bool match = false;
        if (i < N) {
            u32 flat = 0x1FFFFFu - (u32)(ps[i] & 0x1FFFFFu);
            match = (flat % NCC) == (u32)myc;
        }
        u32 m = __ballot_sync(0xffffffffu, match);
        if (match) {
            u32 idx = base + __popc(m & ((1u << lane) - 1u));
            if (idx < CAPC) spos[w][idx] = (u16)i;
        }
        base += __popc(m);
    }
    u32 cnt = min(base, (u32)CAPC);
    float coff = (float)myc * 4096.0f;
    for (u32 j = lane; j < cnt; j += 32) {
        u32 i = spos[w][j];
        u32 flat = 0x1FFFFFu - (u32)(ps[i] & 0x1FFFFFu);
        u32 n = flat / NCC;
        const float* q = pred + ((size_t)b * NN + n) * ROWW;
        float cx = q[0], cy = q[1], ww = q[2], hh = q[3];
        float x1 = __fsub_rn(cx, __fmul_rn(0.5f, ww));
        float y1 = __fsub_rn(cy, __fmul_rn(0.5f, hh));
        float x2 = __fadd_rn(cx, __fmul_rn(0.5f, ww));
        float y2 = __fadd_rn(cy, __fmul_rn(0.5f, hh));
        float ox1 = __fadd_rn(x1, coff), oy1 = __fadd_rn(y1, coff);
        float ox2 = __fadd_rn(x2, coff), oy2 = __fadd_rn(y2, coff);
        sbox[w][j] = make_float4(ox1, oy1, ox2, oy2);
        sarea[w][j] = __fmul_rn(__fsub_rn(ox2, ox1), __fsub_rn(oy2, oy1));
        ssup[w][j] = 0;
    }
    __syncwarp();
    for (u32 m = 0; m < cnt; m++) {
        if (ssup[w][m]) continue;
        if (lane == 0) g_keep[(size_t)b * NPRE + spos[w][m]] = 1;
        float4 bm = sbox[w][m];
        float am = sarea[w][m];
        for (u32 j = m + 1 + lane; j < cnt; j += 32) {
            if (ssup[w][j]) continue;
            float4 bj = sbox[w][j];
            float ltx = fmaxf(bm.x, bj.x), lty = fmaxf(bm.y, bj.y);
            float rbx = fminf(bm.z, bj.z), rby = fminf(bm.w, bj.w);
            float wx = fmaxf(__fsub_rn(rbx, ltx), 0.0f);
            float wy = fmaxf(__fsub_rn(rby, lty), 0.0f);
            float inter = __fmul_rn(wx, wy);
            if (inter > 0.0f) {
                float den = __fadd_rn(__fsub_rn(__fadd_rn(am, sarea[w][j]), inter), 1e-9f);
                if (__fdiv_rn(inter, den) > 0.5f) ssup[w][j] = 1;
            }
        }
        __syncwarp();
    }
}

// ---------------- kernel 4: prefix-scan keep flags, emit first 300 ----------------
__global__ void __launch_bounds__(256) k_final(const float* __restrict__ pred,
                                               float* __restrict__ out) {
    __shared__ u32 part[256];
    int b = blockIdx.x, tid = threadIdx.x;
    u32 N = g_preN[b];
    float* ob = out + (size_t)b * MAXDET * 6;
    for (int k = tid; k < MAXDET * 6; k += 256) ob[k] = 0.0f;
    u32 s = 0;
    unsigned char f[4];
#pragma unroll
    for (int t = 0; t < 4; t++) {
        u32 i = tid * 4 + t;
        f[t] = (i < N) ? g_keep[(size_t)b * NPRE + i] : 0;
        s += f[t];
    }
    part[tid] = s;
    __syncthreads();
    for (int off = 1; off < 256; off <<= 1) {
        u32 v = (tid >= off) ? part[tid - off] : 0;
        __syncthreads();
        part[tid] += v;
        __syncthreads();
    }
    u32 r = part[tid] - s;
#pragma unroll
    for (int t = 0; t < 4; t++) {
        u32 i = tid * 4 + t;
        if (f[t]) {
            if (r < (u32)MAXDET) {
                u64 key = g_preSorted[(size_t)b * NPRE + i];
                u32 flat = 0x1FFFFFu - (u32)(key & 0x1FFFFFu);
                u32 n = flat / NCC, c = flat - n * NCC;
                const float* q = pred + ((size_t)b * NN + n) * ROWW;
                float cx = q[0], cy = q[1], ww = q[2], hh = q[3];
                float* o = ob + r * 6;
                o[0] = __fsub_rn(cx, __fmul_rn(0.5f, ww));
                o[1] = __fsub_rn(cy, __fmul_rn(0.5f, hh));
                o[2] = __fadd_rn(cx, __fmul_rn(0.5f, ww));
                o[3] = __fadd_rn(cy, __fmul_rn(0.5f, hh));
                o[4] = __uint_as_float((u32)(key >> 21));
                o[5] = (float)c;
            }
            r++;
        }
    }
}

extern "C" void kernel_launch(void* const* d_in, const int* in_sizes, int n_in,
                              void* d_out, int out_size) {
    const float* pred = (const float*)d_in[0];
    float* out = (float*)d_out;
    (void)in_sizes; (void)n_in; (void)out_size;

    cudaFuncSetAttribute(k_main, cudaFuncAttributeMaxDynamicSharedMemorySize, GCAP * 8);

    k_pass1<<<dim3(GRID_X, BB), 256>>>(pred);
    k_main<<<BB, 1024, GCAP * 8>>>(pred);
    k_nms<<<dim3(NCC / 8, BB), 256>>>(pred);
    k_final<<<BB, 256>>>(pred, out);
}